// round 2
// baseline (speedup 1.0000x reference)
#include <cuda_runtime.h>
#include <cuda_bf16.h>
#include <mma.h>

using namespace nvcuda;

#define Dh   1024
#define Bn   8
#define Tn   256
#define Vn   32000
#define Rn   2048   // Bn*Tn

// ---------------- scratch (static device allocations; no cudaMalloc) ----------------
__device__ float          g_Wx[Rn * Dh];          // 8 MB
__device__ float          g_h[Rn * Dh];           // 8 MB (hidden states, all t)
__device__ __nv_bfloat16  g_hbf[Rn * Dh];         // 4 MB
__device__ __nv_bfloat16  g_xbf[Rn * Dh];         // 4 MB (embedded inputs, bf16)
__device__ __nv_bfloat16  g_Wbf[Dh * Dh];         // 2 MB
__device__ __nv_bfloat16  g_Woutbf[Vn * Dh];      // 64 MB
__device__ float          g_part[4 * Bn * Dh];    // k-split partials
__device__ unsigned int   g_sync;

// ---------------- elementwise fp32 -> bf16 ----------------
__global__ void cvt_kernel(const float* __restrict__ src, __nv_bfloat16* __restrict__ dst, int n4) {
    int i = blockIdx.x * blockDim.x + threadIdx.x;
    int stride = gridDim.x * blockDim.x;
    for (; i < n4; i += stride) {
        float4 v = ((const float4*)src)[i];
        ((__nv_bfloat162*)dst)[2*i]   = __floats2bfloat162_rn(v.x, v.y);
        ((__nv_bfloat162*)dst)[2*i+1] = __floats2bfloat162_rn(v.z, v.w);
    }
}

// ---------------- embedding gather -> bf16 ----------------
__global__ void embed_kernel(const int* __restrict__ idx, const float* __restrict__ E,
                             __nv_bfloat16* __restrict__ dst) {
    int r = blockIdx.x;                 // 0..2047  (r = b*T + t)
    int id = idx[r];
    const float4* src = (const float4*)(E + (size_t)id * Dh);
    __nv_bfloat162* out = (__nv_bfloat162*)(dst + (size_t)r * Dh);
    for (int i = threadIdx.x; i < Dh / 4; i += blockDim.x) {
        float4 v = src[i];
        out[2*i]   = __floats2bfloat162_rn(v.x, v.y);
        out[2*i+1] = __floats2bfloat162_rn(v.z, v.w);
    }
}

// ---------------- bf16 NT GEMM: C[m,n] = sum_k A[m,k] * B[n,k] ----------------
// Block tile 128x128, K-step 32, 8 warps, warp tile 64x32 (4x2 wmma 16x16x16).
#define BM 128
#define BN 128
#define BK 32
#define SLD 48   // smem leading dim (bf16 elems); 48*2=96B, multiple of 16B

__global__ __launch_bounds__(256) void gemm_nt(const __nv_bfloat16* __restrict__ A,
                                               const __nv_bfloat16* __restrict__ Bm,
                                               float* __restrict__ C,
                                               int Mr, int Nr, int Kr) {
    __shared__ __nv_bfloat16 As[BM * SLD];
    __shared__ __nv_bfloat16 Bs[BN * SLD];
    const int bn = blockIdx.x, bm = blockIdx.y;
    const int tid = threadIdx.x;
    const int w  = tid >> 5;
    const int wm = w & 1;       // 0..1
    const int wn = w >> 1;      // 0..3

    wmma::fragment<wmma::accumulator, 16, 16, 16, float> acc[4][2];
    #pragma unroll
    for (int i = 0; i < 4; i++)
        #pragma unroll
        for (int j = 0; j < 2; j++) wmma::fill_fragment(acc[i][j], 0.0f);

    for (int k0 = 0; k0 < Kr; k0 += BK) {
        // load 128x32 bf16 tiles of A and B: 512 int4 each, 2 per thread
        #pragma unroll
        for (int q = 0; q < 2; q++) {
            int li  = tid * 2 + q;           // 0..511
            int row = li >> 2;               // 0..127
            int c   = (li & 3) * 8;          // bf16 col offset (8 elems = 16B)
            int4 va = *(const int4*)(A  + (size_t)(bm * BM + row) * Kr + k0 + c);
            *(int4*)(As + row * SLD + c) = va;
            int4 vb = *(const int4*)(Bm + (size_t)(bn * BN + row) * Kr + k0 + c);
            *(int4*)(Bs + row * SLD + c) = vb;
        }
        __syncthreads();
        #pragma unroll
        for (int kk = 0; kk < BK; kk += 16) {
            wmma::fragment<wmma::matrix_a, 16, 16, 16, __nv_bfloat16, wmma::row_major> af[4];
            wmma::fragment<wmma::matrix_b, 16, 16, 16, __nv_bfloat16, wmma::col_major> bf[2];
            #pragma unroll
            for (int i = 0; i < 4; i++)
                wmma::load_matrix_sync(af[i], As + (wm * 64 + i * 16) * SLD + kk, SLD);
            #pragma unroll
            for (int j = 0; j < 2; j++)
                wmma::load_matrix_sync(bf[j], Bs + (wn * 32 + j * 16) * SLD + kk, SLD);
            #pragma unroll
            for (int i = 0; i < 4; i++)
                #pragma unroll
                for (int j = 0; j < 2; j++)
                    wmma::mma_sync(acc[i][j], af[i], bf[j], acc[i][j]);
        }
        __syncthreads();
    }
    #pragma unroll
    for (int i = 0; i < 4; i++)
        #pragma unroll
        for (int j = 0; j < 2; j++) {
            float* cp = C + (size_t)(bm * BM + wm * 64 + i * 16) * Nr + bn * BN + wn * 32 + j * 16;
            wmma::store_matrix_sync(cp, acc[i][j], Nr, wmma::mem_row_major);
        }
}

// ---------------- persistent recurrence kernel ----------------
// 128 blocks x 256 threads (co-resident on 148 SMs).
// warp covers (32 e's = lanes) x (k-chunk of 32); block = 1 e-group x 8 k-chunks.
// U held in registers; h loads are warp-uniform (broadcast).
__device__ __forceinline__ void grid_sync_fn(unsigned int epoch) {
    __syncthreads();
    if (threadIdx.x == 0) {
        __threadfence();
        atomicAdd(&g_sync, 1u);
        const unsigned int target = epoch * 128u;
        while (*(volatile unsigned int*)&g_sync < target) { }
        __threadfence();
    }
    __syncthreads();
}

__global__ void reset_sync_kernel() { g_sync = 0u; }

__global__ __launch_bounds__(256) void rnn_kernel(const float* __restrict__ Ug,
                                                  const float* __restrict__ bWv,
                                                  const float* __restrict__ bUv) {
    const int tid  = threadIdx.x;
    const int w    = tid >> 5;
    const int lane = tid & 31;
    const int bi   = blockIdx.x;
    const int eg   = bi >> 2;               // 0..31
    const int kq   = bi & 3;                // k-quarter
    const int kc   = kq * 8 + w;            // 0..31
    const int e    = eg * 32 + lane;        // 0..1023
    const int k0   = kc * 32;

    float Ur[32];
    #pragma unroll
    for (int j = 0; j < 32; j++) Ur[j] = Ug[(size_t)e * Dh + k0 + j];

    __shared__ float sp[8 * 256];
    unsigned int epoch = 0;

    for (int t = 0; t < Tn; t++) {
        float acc[8];
        #pragma unroll
        for (int b = 0; b < 8; b++) acc[b] = 0.0f;

        if (t > 0) {
            #pragma unroll
            for (int b = 0; b < 8; b++) {
                const float4* hp = (const float4*)(g_h + (size_t)(b * Tn + t - 1) * Dh + k0);
                #pragma unroll
                for (int jj = 0; jj < 8; jj++) {
                    float4 h4 = __ldcg(hp + jj);
                    acc[b] = fmaf(Ur[4*jj+0], h4.x, acc[b]);
                    acc[b] = fmaf(Ur[4*jj+1], h4.y, acc[b]);
                    acc[b] = fmaf(Ur[4*jj+2], h4.z, acc[b]);
                    acc[b] = fmaf(Ur[4*jj+3], h4.w, acc[b]);
                }
            }
        }

        // block-level reduction over the 8 warps (8 k-chunks)
        #pragma unroll
        for (int b = 0; b < 8; b++) sp[w * 256 + b * 32 + lane] = acc[b];
        __syncthreads();
        {
            float s = sp[tid] + sp[256 + tid] + sp[512 + tid] + sp[768 + tid]
                    + sp[1024 + tid] + sp[1280 + tid] + sp[1536 + tid] + sp[1792 + tid];
            int b  = tid >> 5;
            int el = tid & 31;
            g_part[kq * (Bn * Dh) + b * Dh + eg * 32 + el] = s;
        }
        epoch++; grid_sync_fn(epoch);

        // phase B: 8192 outputs on blocks 0..31
        if (bi < 32) {
            int oid = bi * 256 + tid;
            int b   = oid >> 10;
            int e2  = oid & 1023;
            float s = __ldcg(&g_part[b * Dh + e2])
                    + __ldcg(&g_part[1 * (Bn * Dh) + b * Dh + e2])
                    + __ldcg(&g_part[2 * (Bn * Dh) + b * Dh + e2])
                    + __ldcg(&g_part[3 * (Bn * Dh) + b * Dh + e2]);
            s += g_Wx[(size_t)(b * Tn + t) * Dh + e2] + bWv[e2] + bUv[e2];
            float h = tanhf(s);
            g_h[(size_t)(b * Tn + t) * Dh + e2]   = h;
            g_hbf[(size_t)(b * Tn + t) * Dh + e2] = __float2bfloat16(h);
        }
        epoch++; grid_sync_fn(epoch);
    }
}

// ---------------- log_softmax: one block per row, bias folded in ----------------
__global__ __launch_bounds__(256) void lse_kernel(float* __restrict__ C, const float* __restrict__ bout) {
    const int r = blockIdx.x;
    float* row = C + (size_t)r * Vn;
    __shared__ float red[256];

    float m = -1e30f;
    for (int i = threadIdx.x; i < Vn; i += 256) m = fmaxf(m, row[i] + bout[i]);
    red[threadIdx.x] = m;
    __syncthreads();
    for (int s = 128; s > 0; s >>= 1) {
        if (threadIdx.x < s) red[threadIdx.x] = fmaxf(red[threadIdx.x], red[threadIdx.x + s]);
        __syncthreads();
    }
    m = red[0];
    __syncthreads();

    float sum = 0.0f;
    for (int i = threadIdx.x; i < Vn; i += 256) sum += __expf(row[i] + bout[i] - m);
    red[threadIdx.x] = sum;
    __syncthreads();
    for (int s = 128; s > 0; s >>= 1) {
        if (threadIdx.x < s) red[threadIdx.x] += red[threadIdx.x + s];
        __syncthreads();
    }
    float lse = m + __logf(red[0]);

    for (int i = threadIdx.x; i < Vn; i += 256) row[i] = row[i] + bout[i] - lse;
}

// ---------------- launch ----------------
extern "C" void kernel_launch(void* const* d_in, const int* in_sizes, int n_in,
                              void* d_out, int out_size) {
    const int*   idx  = (const int*)d_in[0];
    const float* E    = (const float*)d_in[1];
    const float* W    = (const float*)d_in[2];
    const float* bW   = (const float*)d_in[3];
    const float* U    = (const float*)d_in[4];
    const float* bU   = (const float*)d_in[5];
    const float* Wout = (const float*)d_in[6];
    const float* bout = (const float*)d_in[7];
    float* out = (float*)d_out;

    void *p_xbf, *p_Wbf, *p_Woutbf, *p_Wx, *p_hbf;
    cudaGetSymbolAddress(&p_xbf,    g_xbf);
    cudaGetSymbolAddress(&p_Wbf,    g_Wbf);
    cudaGetSymbolAddress(&p_Woutbf, g_Woutbf);
    cudaGetSymbolAddress(&p_Wx,     g_Wx);
    cudaGetSymbolAddress(&p_hbf,    g_hbf);

    // 1. convert W and Wout to bf16
    cvt_kernel<<<512, 256>>>(W, (__nv_bfloat16*)p_Wbf, Dh * Dh / 4);
    cvt_kernel<<<4096, 256>>>(Wout, (__nv_bfloat16*)p_Woutbf, Vn * Dh / 4);

    // 2. embedding gather -> bf16
    embed_kernel<<<Rn, 256>>>(idx, E, (__nv_bfloat16*)p_xbf);

    // 3. input projection: Wx[r,e] = sum_d x[r,d] * W[e,d]   (bias folded into recurrence)
    gemm_nt<<<dim3(Dh / BN, Rn / BM), 256>>>((const __nv_bfloat16*)p_xbf,
                                             (const __nv_bfloat16*)p_Wbf,
                                             (float*)p_Wx, Rn, Dh, Dh);

    // 4. recurrence (persistent kernel, custom grid sync)
    reset_sync_kernel<<<1, 1>>>();
    rnn_kernel<<<128, 256>>>(U, bW, bU);

    // 5. output projection: logits[r,v] = sum_d h[r,d] * Wout[v,d]  (bout folded into lse)
    gemm_nt<<<dim3(Vn / BN, Rn / BM), 256>>>((const __nv_bfloat16*)p_hbf,
                                             (const __nv_bfloat16*)p_Woutbf,
                                             out, Rn, Vn, Dh);

    // 6. log_softmax in-place (adds bout)
    lse_kernel<<<Rn, 256>>>(out, bout);
}

// round 3
// speedup vs baseline: 1.1630x; 1.1630x over previous
#include <cuda_runtime.h>
#include <cuda_bf16.h>
#include <mma.h>
#include <cstdint>

using namespace nvcuda;

#define Dh   1024
#define Bn   8
#define Tn   256
#define Vn   32000
#define Rn   2048   // Bn*Tn

// ---------------- scratch (static device allocations; no cudaMalloc) ----------------
__device__ float          g_Wx[Rn * Dh];          // 8 MB
__device__ float          g_h[Rn * Dh];           // 8 MB
__device__ __nv_bfloat16  g_hbf[Rn * Dh];         // 4 MB
__device__ __nv_bfloat16  g_xbf[Rn * Dh];         // 4 MB
__device__ __nv_bfloat16  g_Wbf[Dh * Dh];         // 2 MB
__device__ __nv_bfloat16  g_Woutbf[Vn * Dh];      // 64 MB
__device__ float          g_part[4 * Bn * Dh];
__device__ unsigned int   g_sync;

// ---------------- elementwise fp32 -> bf16 ----------------
__global__ void cvt_kernel(const float* __restrict__ src, __nv_bfloat16* __restrict__ dst, int n4) {
    int i = blockIdx.x * blockDim.x + threadIdx.x;
    int stride = gridDim.x * blockDim.x;
    for (; i < n4; i += stride) {
        float4 v = ((const float4*)src)[i];
        ((__nv_bfloat162*)dst)[2*i]   = __floats2bfloat162_rn(v.x, v.y);
        ((__nv_bfloat162*)dst)[2*i+1] = __floats2bfloat162_rn(v.z, v.w);
    }
}

// ---------------- embedding gather -> bf16 ----------------
__global__ void embed_kernel(const int* __restrict__ idx, const float* __restrict__ E,
                             __nv_bfloat16* __restrict__ dst) {
    int r = blockIdx.x;
    int id = idx[r];
    const float4* src = (const float4*)(E + (size_t)id * Dh);
    __nv_bfloat162* out = (__nv_bfloat162*)(dst + (size_t)r * Dh);
    for (int i = threadIdx.x; i < Dh / 4; i += blockDim.x) {
        float4 v = src[i];
        out[2*i]   = __floats2bfloat162_rn(v.x, v.y);
        out[2*i+1] = __floats2bfloat162_rn(v.z, v.w);
    }
}

// ---------------- bf16 NT GEMM: C[m,n] = sum_k A[m,k] * B[n,k] ----------------
// 256x128 block tile, BK=32, 3-stage cp.async pipeline, 8 warps with 64x64 warp tiles.
#define BM 256
#define BN 128
#define BK 32
#define NST 3
#define SLD 48   // smem leading dim in bf16 elems (96B rows)

#define A_STAGE (BM * SLD)            // bf16 elems per A stage
#define B_STAGE (BN * SLD)
#define GEMM_SMEM_BYTES (NST * (A_STAGE + B_STAGE) * 2)

__device__ __forceinline__ void cp_async16(uint32_t dst, const void* src) {
    asm volatile("cp.async.cg.shared.global [%0], [%1], 16;" :: "r"(dst), "l"(src));
}
__device__ __forceinline__ void cp_commit() { asm volatile("cp.async.commit_group;"); }

__global__ __launch_bounds__(256, 1) void gemm_nt(const __nv_bfloat16* __restrict__ A,
                                                  const __nv_bfloat16* __restrict__ Bm,
                                                  float* __restrict__ C,
                                                  int Mr, int Nr, int Kr) {
    extern __shared__ __nv_bfloat16 smem[];
    __nv_bfloat16* As = smem;                       // NST stages of BM x SLD
    __nv_bfloat16* Bs = smem + NST * A_STAGE;       // NST stages of BN x SLD

    const int bn = blockIdx.x, bm = blockIdx.y;
    const int tid = threadIdx.x;
    const int w  = tid >> 5;
    const int wm = w >> 1;      // 0..3 (64-row slab)
    const int wn = w & 1;       // 0..1 (64-col slab)

    // ---- load task mapping ----
    // A tile: 256 rows x 32 cols bf16 = 1024 x 16B chunks -> 4 per thread
    // B tile: 128 rows x 32 cols          = 512 chunks    -> 2 per thread
    int a_row[4], a_col[4];
    #pragma unroll
    for (int q = 0; q < 4; q++) {
        int task = q * 256 + tid;
        a_row[q] = task >> 2;
        a_col[q] = (task & 3) * 8;
    }
    int b_row[2], b_col[2];
    #pragma unroll
    for (int q = 0; q < 2; q++) {
        int task = q * 256 + tid;
        b_row[q] = task >> 2;
        b_col[q] = (task & 3) * 8;
    }
    const __nv_bfloat16* Abase = A  + (size_t)(bm * BM) * Kr;
    const __nv_bfloat16* Bbase = Bm + (size_t)(bn * BN) * Kr;
    uint32_t sA = (uint32_t)__cvta_generic_to_shared(As);
    uint32_t sB = (uint32_t)__cvta_generic_to_shared(Bs);

    wmma::fragment<wmma::accumulator, 16, 16, 16, float> acc[4][4];
    #pragma unroll
    for (int i = 0; i < 4; i++)
        #pragma unroll
        for (int j = 0; j < 4; j++) wmma::fill_fragment(acc[i][j], 0.0f);

    const int KT = Kr / BK;

    auto issue_stage = [&](int st, int k0) {
        uint32_t aOff = sA + st * (A_STAGE * 2);
        uint32_t bOff = sB + st * (B_STAGE * 2);
        #pragma unroll
        for (int q = 0; q < 4; q++)
            cp_async16(aOff + (a_row[q] * SLD + a_col[q]) * 2,
                       Abase + (size_t)a_row[q] * Kr + k0 + a_col[q]);
        #pragma unroll
        for (int q = 0; q < 2; q++)
            cp_async16(bOff + (b_row[q] * SLD + b_col[q]) * 2,
                       Bbase + (size_t)b_row[q] * Kr + k0 + b_col[q]);
    };

    // prologue: stages 0..NST-2
    #pragma unroll
    for (int s = 0; s < NST - 1; s++) { issue_stage(s, s * BK); cp_commit(); }

    int st = 0;
    for (int i = 0; i < KT; i++) {
        asm volatile("cp.async.wait_group %0;" :: "n"(NST - 2));
        __syncthreads();

        int nf = i + NST - 1;
        if (nf < KT) issue_stage(nf % NST, nf * BK);
        cp_commit();

        const __nv_bfloat16* Ast = As + st * A_STAGE;
        const __nv_bfloat16* Bst = Bs + st * B_STAGE;
        #pragma unroll
        for (int kk = 0; kk < BK; kk += 16) {
            wmma::fragment<wmma::matrix_a, 16, 16, 16, __nv_bfloat16, wmma::row_major> af[4];
            wmma::fragment<wmma::matrix_b, 16, 16, 16, __nv_bfloat16, wmma::col_major> bf[4];
            #pragma unroll
            for (int ii = 0; ii < 4; ii++)
                wmma::load_matrix_sync(af[ii], Ast + (wm * 64 + ii * 16) * SLD + kk, SLD);
            #pragma unroll
            for (int jj = 0; jj < 4; jj++)
                wmma::load_matrix_sync(bf[jj], Bst + (wn * 64 + jj * 16) * SLD + kk, SLD);
            #pragma unroll
            for (int ii = 0; ii < 4; ii++)
                #pragma unroll
                for (int jj = 0; jj < 4; jj++)
                    wmma::mma_sync(acc[ii][jj], af[ii], bf[jj], acc[ii][jj]);
        }
        st++; if (st == NST) st = 0;
    }

    #pragma unroll
    for (int ii = 0; ii < 4; ii++)
        #pragma unroll
        for (int jj = 0; jj < 4; jj++) {
            float* cp = C + (size_t)(bm * BM + wm * 64 + ii * 16) * Nr + bn * BN + wn * 64 + jj * 16;
            wmma::store_matrix_sync(cp, acc[ii][jj], Nr, wmma::mem_row_major);
        }
}

// ---------------- persistent recurrence kernel (packed f32x2 FMA) ----------------
__device__ __forceinline__ unsigned long long pack2(float x, float y) {
    unsigned long long r;
    asm("mov.b64 %0, {%1, %2};" : "=l"(r) : "f"(x), "f"(y));
    return r;
}
__device__ __forceinline__ void unpack2(unsigned long long p, float& x, float& y) {
    asm("mov.b64 {%0, %1}, %2;" : "=f"(x), "=f"(y) : "l"(p));
}
#define FMA2(d, a, b, c) asm("fma.rn.f32x2 %0, %1, %2, %3;" : "=l"(d) : "l"(a), "l"(b), "l"(c))

__device__ __forceinline__ void grid_sync_fn(unsigned int epoch) {
    __syncthreads();
    if (threadIdx.x == 0) {
        __threadfence();
        atomicAdd(&g_sync, 1u);
        const unsigned int target = epoch * 128u;
        while (*(volatile unsigned int*)&g_sync < target) { }
        __threadfence();
    }
    __syncthreads();
}

__global__ void reset_sync_kernel() { g_sync = 0u; }

__global__ __launch_bounds__(256) void rnn_kernel(const float* __restrict__ Ug,
                                                  const float* __restrict__ bWv,
                                                  const float* __restrict__ bUv) {
    const int tid  = threadIdx.x;
    const int w    = tid >> 5;
    const int lane = tid & 31;
    const int bi   = blockIdx.x;
    const int eg   = bi >> 2;
    const int kq   = bi & 3;
    const int kc   = kq * 8 + w;
    const int e    = eg * 32 + lane;
    const int k0   = kc * 32;

    unsigned long long Up[16];
    #pragma unroll
    for (int j = 0; j < 16; j++) {
        float2 u2 = *(const float2*)(Ug + (size_t)e * Dh + k0 + 2 * j);
        Up[j] = pack2(u2.x, u2.y);
    }

    __shared__ float sp[8 * 256];
    unsigned int epoch = 0;

    for (int t = 0; t < Tn; t++) {
        unsigned long long accP[8];
        #pragma unroll
        for (int b = 0; b < 8; b++) accP[b] = 0ULL;

        if (t > 0) {
            #pragma unroll
            for (int b = 0; b < 8; b++) {
                const float4* hp = (const float4*)(g_h + (size_t)(b * Tn + t - 1) * Dh + k0);
                #pragma unroll
                for (int jj = 0; jj < 8; jj++) {
                    float4 h4 = __ldcg(hp + jj);
                    unsigned long long h0 = pack2(h4.x, h4.y);
                    unsigned long long h1 = pack2(h4.z, h4.w);
                    FMA2(accP[b], Up[2*jj],   h0, accP[b]);
                    FMA2(accP[b], Up[2*jj+1], h1, accP[b]);
                }
            }
        }

        #pragma unroll
        for (int b = 0; b < 8; b++) {
            float lo, hi; unpack2(accP[b], lo, hi);
            sp[w * 256 + b * 32 + lane] = lo + hi;
        }
        __syncthreads();
        {
            float s = sp[tid] + sp[256 + tid] + sp[512 + tid] + sp[768 + tid]
                    + sp[1024 + tid] + sp[1280 + tid] + sp[1536 + tid] + sp[1792 + tid];
            int b  = tid >> 5;
            int el = tid & 31;
            g_part[kq * (Bn * Dh) + b * Dh + eg * 32 + el] = s;
        }
        epoch++; grid_sync_fn(epoch);

        if (bi < 32) {
            int oid = bi * 256 + tid;
            int b   = oid >> 10;
            int e2  = oid & 1023;
            float s = __ldcg(&g_part[b * Dh + e2])
                    + __ldcg(&g_part[1 * (Bn * Dh) + b * Dh + e2])
                    + __ldcg(&g_part[2 * (Bn * Dh) + b * Dh + e2])
                    + __ldcg(&g_part[3 * (Bn * Dh) + b * Dh + e2]);
            s += g_Wx[(size_t)(b * Tn + t) * Dh + e2] + bWv[e2] + bUv[e2];
            float h = tanhf(s);
            g_h[(size_t)(b * Tn + t) * Dh + e2]   = h;
            g_hbf[(size_t)(b * Tn + t) * Dh + e2] = __float2bfloat16(h);
        }
        epoch++; grid_sync_fn(epoch);
    }
}

// ---------------- log_softmax: online max/sum (2 read passes), bias folded in ----------------
__global__ __launch_bounds__(256) void lse_kernel(float* __restrict__ C, const float* __restrict__ bout) {
    const int r = blockIdx.x;
    float* row = C + (size_t)r * Vn;
    __shared__ float redm[256];
    __shared__ float reds[256];

    float m = -1e30f, s = 0.0f;
    for (int i = threadIdx.x; i < Vn; i += 256) {
        float x = row[i] + bout[i];
        if (x > m) { s = s * __expf(m - x) + 1.0f; m = x; }
        else       { s += __expf(x - m); }
    }
    redm[threadIdx.x] = m;
    reds[threadIdx.x] = s;
    __syncthreads();
    for (int st = 128; st > 0; st >>= 1) {
        if (threadIdx.x < st) {
            float m2 = redm[threadIdx.x + st], s2 = reds[threadIdx.x + st];
            float m1 = redm[threadIdx.x],      s1 = reds[threadIdx.x];
            float mn = fmaxf(m1, m2);
            redm[threadIdx.x] = mn;
            reds[threadIdx.x] = s1 * __expf(m1 - mn) + s2 * __expf(m2 - mn);
        }
        __syncthreads();
    }
    float lse = redm[0] + __logf(reds[0]);

    for (int i = threadIdx.x; i < Vn; i += 256) row[i] = row[i] + bout[i] - lse;
}

// ---------------- launch ----------------
extern "C" void kernel_launch(void* const* d_in, const int* in_sizes, int n_in,
                              void* d_out, int out_size) {
    const int*   idx  = (const int*)d_in[0];
    const float* E    = (const float*)d_in[1];
    const float* W    = (const float*)d_in[2];
    const float* bW   = (const float*)d_in[3];
    const float* U    = (const float*)d_in[4];
    const float* bU   = (const float*)d_in[5];
    const float* Wout = (const float*)d_in[6];
    const float* bout = (const float*)d_in[7];
    float* out = (float*)d_out;

    void *p_xbf, *p_Wbf, *p_Woutbf, *p_Wx, *p_hbf;
    cudaGetSymbolAddress(&p_xbf,    g_xbf);
    cudaGetSymbolAddress(&p_Wbf,    g_Wbf);
    cudaGetSymbolAddress(&p_Woutbf, g_Woutbf);
    cudaGetSymbolAddress(&p_Wx,     g_Wx);
    cudaGetSymbolAddress(&p_hbf,    g_hbf);

    static int attr_set = 0;
    if (!attr_set) {
        cudaFuncSetAttribute(gemm_nt, cudaFuncAttributeMaxDynamicSharedMemorySize, GEMM_SMEM_BYTES);
        attr_set = 1;
    }

    cvt_kernel<<<512, 256>>>(W, (__nv_bfloat16*)p_Wbf, Dh * Dh / 4);
    cvt_kernel<<<4096, 256>>>(Wout, (__nv_bfloat16*)p_Woutbf, Vn * Dh / 4);

    embed_kernel<<<Rn, 256>>>(idx, E, (__nv_bfloat16*)p_xbf);

    gemm_nt<<<dim3(Dh / BN, Rn / BM), 256, GEMM_SMEM_BYTES>>>(
        (const __nv_bfloat16*)p_xbf, (const __nv_bfloat16*)p_Wbf, (float*)p_Wx, Rn, Dh, Dh);

    reset_sync_kernel<<<1, 1>>>();
    rnn_kernel<<<128, 256>>>(U, bW, bU);

    gemm_nt<<<dim3(Vn / BN, Rn / BM), 256, GEMM_SMEM_BYTES>>>(
        (const __nv_bfloat16*)p_hbf, (const __nv_bfloat16*)p_Woutbf, out, Rn, Vn, Dh);

    lse_kernel<<<Rn, 256>>>(out, bout);
}

// round 5
// speedup vs baseline: 1.3420x; 1.1539x over previous
#include <cuda_runtime.h>
#include <cuda_bf16.h>
#include <cstdint>

#define Dh   1024
#define Bn   8
#define Tn   256
#define Vn   32000
#define Rn   2048   // Bn*Tn

// ---------------- scratch (static device allocations; no cudaMalloc) ----------------
__device__ float          g_Wx[Rn * Dh];          // 8 MB
__device__ float          g_h[Rn * Dh];           // 8 MB
__device__ __nv_bfloat16  g_hbf[Rn * Dh];         // 4 MB
__device__ __nv_bfloat16  g_xbf[Rn * Dh];         // 4 MB
__device__ __nv_bfloat16  g_Wbf[Dh * Dh];         // 2 MB
__device__ __nv_bfloat16  g_Woutbf[Vn * Dh];      // 64 MB
__device__ float          g_part[4 * Bn * Dh];
__device__ unsigned int   g_sync;

// ---------------- elementwise fp32 -> bf16 ----------------
__global__ void cvt_kernel(const float* __restrict__ src, __nv_bfloat16* __restrict__ dst, int n4) {
    int i = blockIdx.x * blockDim.x + threadIdx.x;
    int stride = gridDim.x * blockDim.x;
    for (; i < n4; i += stride) {
        float4 v = ((const float4*)src)[i];
        ((__nv_bfloat162*)dst)[2*i]   = __floats2bfloat162_rn(v.x, v.y);
        ((__nv_bfloat162*)dst)[2*i+1] = __floats2bfloat162_rn(v.z, v.w);
    }
}

// ---------------- embedding gather -> bf16 ----------------
__global__ void embed_kernel(const int* __restrict__ idx, const float* __restrict__ E,
                             __nv_bfloat16* __restrict__ dst) {
    int r = blockIdx.x;
    int id = idx[r];
    const float4* src = (const float4*)(E + (size_t)id * Dh);
    __nv_bfloat162* out = (__nv_bfloat162*)(dst + (size_t)r * Dh);
    for (int i = threadIdx.x; i < Dh / 4; i += blockDim.x) {
        float4 v = src[i];
        out[2*i]   = __floats2bfloat162_rn(v.x, v.y);
        out[2*i+1] = __floats2bfloat162_rn(v.z, v.w);
    }
}

// ================= raw mma.sync bf16 NT GEMM: C[m,n] = sum_k A[m,k]*B[n,k] =================
// BM=128 BN=128 BK=64, 3-stage cp.async, 8 warps (2m x 4n), warp tile 64x32.
// SMEM rows are 128B (64 bf16) with XOR swizzle: phys_col = col ^ ((row&7)<<4).
#define BM 128
#define BN 128
#define BK 64
#define NST 3
#define AST (BM * BK * 2)   // 16384 B per A stage
#define BST (BN * BK * 2)   // 16384 B per B stage
#define GEMM_DSMEM (NST * (AST + BST))   // 96 KB

__device__ __forceinline__ uint32_t smem_u32(const void* p) {
    uint32_t a;
    asm("{ .reg .u64 t; cvta.to.shared.u64 t, %1; cvt.u32.u64 %0, t; }" : "=r"(a) : "l"(p));
    return a;
}
__device__ __forceinline__ void cp_async16(uint32_t dst, const void* src) {
    asm volatile("cp.async.cg.shared.global [%0], [%1], 16;" :: "r"(dst), "l"(src));
}
__device__ __forceinline__ void cp_commit() { asm volatile("cp.async.commit_group;"); }

__device__ __forceinline__ void ldsm4(uint32_t& r0, uint32_t& r1, uint32_t& r2, uint32_t& r3, uint32_t a) {
    asm volatile("ldmatrix.sync.aligned.m8n8.x4.shared.b16 {%0,%1,%2,%3}, [%4];"
                 : "=r"(r0), "=r"(r1), "=r"(r2), "=r"(r3) : "r"(a));
}
__device__ __forceinline__ void mma16816(float* d, const uint32_t* a, const uint32_t* b) {
    asm volatile("mma.sync.aligned.m16n8k16.row.col.f32.bf16.bf16.f32 "
                 "{%0,%1,%2,%3}, {%4,%5,%6,%7}, {%8,%9}, {%0,%1,%2,%3};"
                 : "+f"(d[0]), "+f"(d[1]), "+f"(d[2]), "+f"(d[3])
                 : "r"(a[0]), "r"(a[1]), "r"(a[2]), "r"(a[3]), "r"(b[0]), "r"(b[1]));
}

__global__ __launch_bounds__(256, 2) void gemm_mma(const __nv_bfloat16* __restrict__ A,
                                                   const __nv_bfloat16* __restrict__ Bm,
                                                   float* __restrict__ C,
                                                   int Nr, int Kr) {
    extern __shared__ char smem[];
    const uint32_t sBase = smem_u32(smem);
    const uint32_t aS = sBase;
    const uint32_t bS = sBase + NST * AST;

    const int tid  = threadIdx.x;
    const int lane = tid & 31;
    const int wid  = tid >> 5;
    const int wm   = wid >> 2;        // 0..1  (64-row slab)
    const int wn   = wid & 3;         // 0..3  (32-col slab)
    const int bm = blockIdx.x, bn = blockIdx.y;
    const int KTILES = Kr / BK;

    const __nv_bfloat16* Ag = A  + (size_t)(bm * BM) * Kr;
    const __nv_bfloat16* Bg = Bm + (size_t)(bn * BN) * Kr;

    // ---- ldmatrix per-lane address components ----
    // A frag i (m16): row = wm*64 + i*16 + (lane&15); chunk16 = lane>>4
    uint32_t aRowTerm[4], aPhase[4];
    const uint32_t aChunk = (uint32_t)(lane >> 4) * 16;
    #pragma unroll
    for (int i = 0; i < 4; i++) {
        int r = wm * 64 + i * 16 + (lane & 15);
        aRowTerm[i] = (uint32_t)r * 128;
        aPhase[i]   = (uint32_t)(r & 7) << 4;
    }
    // B frag-pair j (n16): n = wn*32 + j*16 + (lane&7) + (lane>>4)*8; chunk = (lane>>3)&1
    uint32_t bRowTerm[2], bPhase[2];
    const uint32_t bChunk = (uint32_t)((lane >> 3) & 1) * 16;
    #pragma unroll
    for (int j = 0; j < 2; j++) {
        int n = wn * 32 + j * 16 + (lane & 7) + ((lane >> 4) << 3);
        bRowTerm[j] = (uint32_t)n * 128;
        bPhase[j]   = (uint32_t)(n & 7) << 4;
    }

    // ---- cp.async task mapping: 1024 16B chunks per stage per matrix, 4/thread ----
    auto load_stage = [&](int st, int kt) {
        const int k0 = kt * BK;
        const uint32_t aOff = aS + st * AST;
        const uint32_t bOff = bS + st * BST;
        #pragma unroll
        for (int q = 0; q < 4; q++) {
            int task = q * 256 + tid;
            int row = task >> 3, ch = task & 7;
            uint32_t col = (uint32_t)ch * 16;
            uint32_t phys = (uint32_t)row * 128 + (col ^ ((uint32_t)(row & 7) << 4));
            cp_async16(aOff + phys, Ag + (size_t)row * Kr + k0 + ch * 8);
            cp_async16(bOff + phys, Bg + (size_t)row * Kr + k0 + ch * 8);
        }
    };

    float acc[4][4][4];
    #pragma unroll
    for (int i = 0; i < 4; i++)
        #pragma unroll
        for (int j = 0; j < 4; j++)
            #pragma unroll
            for (int e = 0; e < 4; e++) acc[i][j][e] = 0.0f;

    load_stage(0, 0); cp_commit();
    load_stage(1, 1); cp_commit();

    for (int kt = 0; kt < KTILES; kt++) {
        const int st = kt % NST;
        asm volatile("cp.async.wait_group 1;" ::: "memory");
        __syncthreads();

        const int nf = kt + 2;
        if (nf < KTILES) load_stage(nf % NST, nf);
        cp_commit();

        const uint32_t aStage = aS + st * AST;
        const uint32_t bStage = bS + st * BST;
        #pragma unroll
        for (int s = 0; s < BK / 16; s++) {
            const uint32_t colA = (uint32_t)s * 32 + aChunk;
            const uint32_t colB = (uint32_t)s * 32 + bChunk;
            uint32_t a[4][4];
            #pragma unroll
            for (int i = 0; i < 4; i++)
                ldsm4(a[i][0], a[i][1], a[i][2], a[i][3],
                      aStage + aRowTerm[i] + (colA ^ aPhase[i]));
            uint32_t b[4][2];
            #pragma unroll
            for (int j = 0; j < 2; j++) {
                uint32_t r0, r1, r2, r3;
                ldsm4(r0, r1, r2, r3, bStage + bRowTerm[j] + (colB ^ bPhase[j]));
                b[2*j][0] = r0; b[2*j][1] = r1;
                b[2*j+1][0] = r2; b[2*j+1][1] = r3;
            }
            #pragma unroll
            for (int i = 0; i < 4; i++)
                #pragma unroll
                for (int j = 0; j < 4; j++)
                    mma16816(acc[i][j], a[i], b[j]);
        }
    }

    // ---- epilogue ----
    const int g = lane >> 2, tg = lane & 3;
    #pragma unroll
    for (int i = 0; i < 4; i++) {
        int row0 = bm * BM + wm * 64 + i * 16 + g;
        #pragma unroll
        for (int j = 0; j < 4; j++) {
            int col = bn * BN + wn * 32 + j * 8 + tg * 2;
            float2 v0 = make_float2(acc[i][j][0], acc[i][j][1]);
            float2 v1 = make_float2(acc[i][j][2], acc[i][j][3]);
            *(float2*)(C + (size_t)row0 * Nr + col)       = v0;
            *(float2*)(C + (size_t)(row0 + 8) * Nr + col) = v1;
        }
    }
}

// ---------------- persistent recurrence kernel (packed f32x2 FMA) ----------------
__device__ __forceinline__ unsigned long long pack2(float x, float y) {
    unsigned long long r;
    asm("mov.b64 %0, {%1, %2};" : "=l"(r) : "f"(x), "f"(y));
    return r;
}
__device__ __forceinline__ void unpack2(unsigned long long p, float& x, float& y) {
    asm("mov.b64 {%0, %1}, %2;" : "=f"(x), "=f"(y) : "l"(p));
}
#define FMA2(d, a, b, c) asm("fma.rn.f32x2 %0, %1, %2, %3;" : "=l"(d) : "l"(a), "l"(b), "l"(c))

__device__ __forceinline__ void grid_sync_fn(unsigned int epoch) {
    __syncthreads();
    if (threadIdx.x == 0) {
        __threadfence();
        atomicAdd(&g_sync, 1u);
        const unsigned int target = epoch * 128u;
        while (*(volatile unsigned int*)&g_sync < target) { }
        __threadfence();
    }
    __syncthreads();
}

__global__ void reset_sync_kernel() { g_sync = 0u; }

__global__ __launch_bounds__(256) void rnn_kernel(const float* __restrict__ Ug,
                                                  const float* __restrict__ bWv,
                                                  const float* __restrict__ bUv) {
    const int tid  = threadIdx.x;
    const int w    = tid >> 5;
    const int lane = tid & 31;
    const int bi   = blockIdx.x;
    const int eg   = bi >> 2;
    const int kq   = bi & 3;
    const int kc   = kq * 8 + w;
    const int e    = eg * 32 + lane;
    const int k0   = kc * 32;

    unsigned long long Up[16];
    #pragma unroll
    for (int j = 0; j < 16; j++) {
        float2 u2 = *(const float2*)(Ug + (size_t)e * Dh + k0 + 2 * j);
        Up[j] = pack2(u2.x, u2.y);
    }

    __shared__ float sp[8 * 256];
    unsigned int epoch = 0;

    for (int t = 0; t < Tn; t++) {
        unsigned long long accP[8];
        #pragma unroll
        for (int b = 0; b < 8; b++) accP[b] = 0ULL;

        if (t > 0) {
            #pragma unroll
            for (int b = 0; b < 8; b++) {
                const float4* hp = (const float4*)(g_h + (size_t)(b * Tn + t - 1) * Dh + k0);
                #pragma unroll
                for (int jj = 0; jj < 8; jj++) {
                    float4 h4 = __ldcg(hp + jj);
                    unsigned long long h0 = pack2(h4.x, h4.y);
                    unsigned long long h1 = pack2(h4.z, h4.w);
                    FMA2(accP[b], Up[2*jj],   h0, accP[b]);
                    FMA2(accP[b], Up[2*jj+1], h1, accP[b]);
                }
            }
        }

        #pragma unroll
        for (int b = 0; b < 8; b++) {
            float lo, hi; unpack2(accP[b], lo, hi);
            sp[w * 256 + b * 32 + lane] = lo + hi;
        }
        __syncthreads();
        {
            float s = sp[tid] + sp[256 + tid] + sp[512 + tid] + sp[768 + tid]
                    + sp[1024 + tid] + sp[1280 + tid] + sp[1536 + tid] + sp[1792 + tid];
            int b  = tid >> 5;
            int el = tid & 31;
            g_part[kq * (Bn * Dh) + b * Dh + eg * 32 + el] = s;
        }
        epoch++; grid_sync_fn(epoch);

        if (bi < 32) {
            int oid = bi * 256 + tid;
            int b   = oid >> 10;
            int e2  = oid & 1023;
            float s = __ldcg(&g_part[b * Dh + e2])
                    + __ldcg(&g_part[1 * (Bn * Dh) + b * Dh + e2])
                    + __ldcg(&g_part[2 * (Bn * Dh) + b * Dh + e2])
                    + __ldcg(&g_part[3 * (Bn * Dh) + b * Dh + e2]);
            s += g_Wx[(size_t)(b * Tn + t) * Dh + e2] + bWv[e2] + bUv[e2];
            float h = tanhf(s);
            g_h[(size_t)(b * Tn + t) * Dh + e2]   = h;
            g_hbf[(size_t)(b * Tn + t) * Dh + e2] = __float2bfloat16(h);
        }
        epoch++; grid_sync_fn(epoch);
    }
}

// ---------------- log_softmax: online max/sum, bias folded in ----------------
__global__ __launch_bounds__(256) void lse_kernel(float* __restrict__ C, const float* __restrict__ bout) {
    const int r = blockIdx.x;
    float* row = C + (size_t)r * Vn;
    __shared__ float redm[256];
    __shared__ float reds[256];

    float m = -1e30f, s = 0.0f;
    for (int i = threadIdx.x; i < Vn; i += 256) {
        float x = row[i] + bout[i];
        if (x > m) { s = s * __expf(m - x) + 1.0f; m = x; }
        else       { s += __expf(x - m); }
    }
    redm[threadIdx.x] = m;
    reds[threadIdx.x] = s;
    __syncthreads();
    for (int st = 128; st > 0; st >>= 1) {
        if (threadIdx.x < st) {
            float m2 = redm[threadIdx.x + st], s2 = reds[threadIdx.x + st];
            float m1 = redm[threadIdx.x],      s1 = reds[threadIdx.x];
            float mn = fmaxf(m1, m2);
            redm[threadIdx.x] = mn;
            reds[threadIdx.x] = s1 * __expf(m1 - mn) + s2 * __expf(m2 - mn);
        }
        __syncthreads();
    }
    float lse = redm[0] + __logf(reds[0]);

    for (int i = threadIdx.x; i < Vn; i += 256) row[i] = row[i] + bout[i] - lse;
}

// ---------------- launch ----------------
extern "C" void kernel_launch(void* const* d_in, const int* in_sizes, int n_in,
                              void* d_out, int out_size) {
    const int*   idx  = (const int*)d_in[0];
    const float* E    = (const float*)d_in[1];
    const float* W    = (const float*)d_in[2];
    const float* bW   = (const float*)d_in[3];
    const float* U    = (const float*)d_in[4];
    const float* bU   = (const float*)d_in[5];
    const float* Wout = (const float*)d_in[6];
    const float* bout = (const float*)d_in[7];
    float* out = (float*)d_out;

    void *p_xbf, *p_Wbf, *p_Woutbf, *p_Wx, *p_hbf;
    cudaGetSymbolAddress(&p_xbf,    g_xbf);
    cudaGetSymbolAddress(&p_Wbf,    g_Wbf);
    cudaGetSymbolAddress(&p_Woutbf, g_Woutbf);
    cudaGetSymbolAddress(&p_Wx,     g_Wx);
    cudaGetSymbolAddress(&p_hbf,    g_hbf);

    static int attr_set = 0;
    if (!attr_set) {
        cudaFuncSetAttribute(gemm_mma, cudaFuncAttributeMaxDynamicSharedMemorySize, GEMM_DSMEM);
        attr_set = 1;
    }

    cvt_kernel<<<512, 256>>>(W, (__nv_bfloat16*)p_Wbf, Dh * Dh / 4);
    cvt_kernel<<<4096, 256>>>(Wout, (__nv_bfloat16*)p_Woutbf, Vn * Dh / 4);

    embed_kernel<<<Rn, 256>>>(idx, E, (__nv_bfloat16*)p_xbf);

    // input projection: Wx[r,e] = sum_d x[r,d] * W[e,d]
    gemm_mma<<<dim3(Rn / BM, Dh / BN), 256, GEMM_DSMEM>>>(
        (const __nv_bfloat16*)p_xbf, (const __nv_bfloat16*)p_Wbf, (float*)p_Wx, Dh, Dh);

    reset_sync_kernel<<<1, 1>>>();
    rnn_kernel<<<128, 256>>>(U, bW, bU);

    // output projection: logits[r,v] = sum_d h[r,d] * Wout[v,d]
    gemm_mma<<<dim3(Rn / BM, Vn / BN), 256, GEMM_DSMEM>>>(
        (const __nv_bfloat16*)p_hbf, (const __nv_bfloat16*)p_Woutbf, out, Vn, Dh);

    lse_kernel<<<Rn, 256>>>(out, bout);
}